// round 11
// baseline (speedup 1.0000x reference)
#include <cuda_runtime.h>
#include <cuda_fp16.h>
#include <cstdint>

#define B_SZ 8192
#define D_SZ 1024
#define E_SZ 32
#define A_SZ 128

// gating weights; fragment-ordered fp16 operands
__device__ float g_weights[B_SZ * E_SZ];
__device__ uint4 g_xh[(size_t)B_SZ * D_SZ / 8];              // 16 MB (8 halves/uint4)
__device__ uint4 g_wh[(size_t)E_SZ * A_SZ * D_SZ / 8];       // 8 MB  (8 halves/uint4)

// ===================== helpers =====================
__device__ __forceinline__ uint32_t smem_u32(const void* p) {
    uint32_t a;
    asm("{ .reg .u64 t; cvta.to.shared.u64 t, %1; cvt.u32.u64 %0, t; }" : "=r"(a) : "l"(p));
    return a;
}
__device__ __forceinline__ uint32_t pk(float a, float b) {
    __half2 h = __floats2half2_rn(a, b);
    return *(uint32_t*)&h;
}
__device__ __forceinline__ void cp16(uint32_t dst, const void* src) {
    asm volatile("cp.async.cg.shared.global [%0], [%1], 16;" :: "r"(dst), "l"(src));
}
#define CP_COMMIT() asm volatile("cp.async.commit_group;" ::: "memory")
#define CP_WAIT4()  asm volatile("cp.async.wait_group 4;" ::: "memory")

// fp16 m16n8k16: D(f32) = A*B + C
__device__ __forceinline__ void mma16(float* c, const uint4& a, uint32_t b0, uint32_t b1) {
    asm volatile(
        "mma.sync.aligned.m16n8k16.row.col.f32.f16.f16.f32 "
        "{%0,%1,%2,%3}, {%4,%5,%6,%7}, {%8,%9}, {%0,%1,%2,%3};"
        : "+f"(c[0]), "+f"(c[1]), "+f"(c[2]), "+f"(c[3])
        : "r"(a.x), "r"(a.y), "r"(a.z), "r"(a.w), "r"(b0), "r"(b1));
}
__device__ __forceinline__ void mma16z(float* c, const uint4& a, uint32_t b0, uint32_t b1) {
    asm volatile(
        "mma.sync.aligned.m16n8k16.row.col.f32.f16.f16.f32 "
        "{%0,%1,%2,%3}, {%4,%5,%6,%7}, {%8,%9}, {%10,%10,%10,%10};"
        : "=f"(c[0]), "=f"(c[1]), "=f"(c[2]), "=f"(c[3])
        : "r"(a.x), "r"(a.y), "r"(a.z), "r"(a.w), "r"(b0), "r"(b1), "f"(0.0f));
}

// =====================================================================
// Prepass A: x -> fp16, fragment-ordered.
// g_xh[(M0*16 + P)*512 + fid*32 + lane] = uint4 A-fragment regs
// fid = (dcsub*2+ks)*4 + mt;  frag covers rows M0*64+mt*16..+15,
// k = P*64 + dcsub*32 + ks*16 .. +15.
// =====================================================================
__global__ __launch_bounds__(256) void convert_x_h(const float* __restrict__ x)
{
    int tid = blockIdx.x * 256 + threadIdx.x;         // 0 .. 1048575
    int lane = tid & 31, fid = (tid >> 5) & 15, P = (tid >> 9) & 15, M0 = tid >> 13;
    int mt = fid & 3, ks = (fid >> 2) & 1, dcsub = fid >> 3;
    int row = M0 * 64 + mt * 16 + (lane >> 2);
    int kb  = P * 64 + dcsub * 32 + ks * 16 + (lane & 3) * 2;
    const float* r0 = x + (size_t)row * D_SZ + kb;
    const float* r1 = r0 + 8 * D_SZ;
    uint4 o;
    o.x = pk(r0[0], r0[1]);      // a0: (row,   k..k+1)
    o.y = pk(r1[0], r1[1]);      // a1: (row+8, k..k+1)
    o.z = pk(r0[8], r0[9]);      // a2: (row,   k+8..k+9)
    o.w = pk(r1[8], r1[9]);      // a3: (row+8, k+8..k+9)
    g_xh[tid] = o;
}

// =====================================================================
// Prepass B: W_strat -> fp16, fragment-ordered.
// g_wh[(((e*16+P)*16 + cb)*2 + dcsub)*32 + lane] =
//   {ks0:b0,b1, ks1:b0,b1} for col a = cb*8 + lane/4.
// =====================================================================
__global__ __launch_bounds__(256) void convert_w_h(const float* __restrict__ W)
{
    int tid = blockIdx.x * 256 + threadIdx.x;         // 0 .. 524287
    int lane = tid & 31, dcsub = (tid >> 5) & 1, cb = (tid >> 6) & 15;
    int P = (tid >> 10) & 15, e = tid >> 14;          // e = 0..31
    int a  = cb * 8 + (lane >> 2);
    int tg = lane & 3;
    const float* base = W + ((size_t)e * A_SZ + a) * D_SZ + P * 64 + dcsub * 32 + tg * 2;
    uint4 o;
    o.x = pk(base[0],  base[1]);    // ks0 b0: k,k+1
    o.y = pk(base[8],  base[9]);    // ks0 b1: k+8,k+9
    o.z = pk(base[16], base[17]);   // ks1 b0
    o.w = pk(base[24], base[25]);   // ks1 b1
    g_wh[tid] = o;
}

// =====================================================================
// Kernel: gating (R1, known-correct). Seeds out with the b_strat bias term.
// =====================================================================
__global__ __launch_bounds__(128) void gating_kernel(
    const float* __restrict__ x, const float* __restrict__ W_att,
    const float* __restrict__ b_att, const float* __restrict__ abias,
    const float* __restrict__ b_strat, const float* __restrict__ gu,
    float* __restrict__ out)
{
    __shared__ float xs[32][64];
    __shared__ float was[32][32];
    __shared__ float L[64][33];
    __shared__ float Wg[64][33];

    const int tid = threadIdx.x;
    const int b0 = blockIdx.x * 64;
    const int tb = tid & 15;
    const int te = tid >> 4;

    float acc[4][4] = {};

    for (int d0 = 0; d0 < D_SZ; d0 += 32) {
        #pragma unroll
        for (int i = 0; i < 4; i++) {
            int f = tid + i * 128;
            int row = f >> 3, c4 = f & 7;
            float4 v = *(const float4*)&x[(size_t)(b0 + row) * D_SZ + d0 + c4 * 4];
            xs[c4 * 4 + 0][row] = v.x; xs[c4 * 4 + 1][row] = v.y;
            xs[c4 * 4 + 2][row] = v.z; xs[c4 * 4 + 3][row] = v.w;
        }
        #pragma unroll
        for (int i = 0; i < 2; i++) {
            int f = tid + i * 128;
            int row = f >> 3, c4 = f & 7;
            float4 v = *(const float4*)&W_att[(size_t)row * D_SZ + d0 + c4 * 4];
            was[c4 * 4 + 0][row] = v.x; was[c4 * 4 + 1][row] = v.y;
            was[c4 * 4 + 2][row] = v.z; was[c4 * 4 + 3][row] = v.w;
        }
        __syncthreads();
        #pragma unroll 8
        for (int kk = 0; kk < 32; kk++) {
            float4 av = *(const float4*)&xs[kk][tb * 4];
            float4 ev = *(const float4*)&was[kk][te * 4];
            float a_[4] = {av.x, av.y, av.z, av.w};
            float e_[4] = {ev.x, ev.y, ev.z, ev.w};
            #pragma unroll
            for (int i = 0; i < 4; i++)
                #pragma unroll
                for (int j = 0; j < 4; j++)
                    acc[i][j] = fmaf(a_[i], e_[j], acc[i][j]);
        }
        __syncthreads();
    }

    #pragma unroll
    for (int i = 0; i < 4; i++)
        #pragma unroll
        for (int j = 0; j < 4; j++)
            L[tb * 4 + i][te * 4 + j] = acc[i][j];
    __syncthreads();

    if (tid < 64) {
        int b = b0 + tid;
        float v[E_SZ];
        float mx = -1e30f;
        #pragma unroll
        for (int e = 0; e < E_SZ; e++) {
            float u = gu[(size_t)b * E_SZ + e];
            float g = -logf(-logf(u + 1e-10f) + 1e-10f);
            float t = L[tid][e] + b_att[e] + abias[e] + g;   // TAU = 1.0
            v[e] = t;
            mx = fmaxf(mx, t);
        }
        float s = 0.f;
        #pragma unroll
        for (int e = 0; e < E_SZ; e++) { v[e] = expf(v[e] - mx); s += v[e]; }
        float inv = 1.f / s;
        #pragma unroll
        for (int e = 0; e < E_SZ; e++) {
            float w = v[e] * inv;
            Wg[tid][e] = w;
            g_weights[(size_t)b * E_SZ + e] = w;
        }
    }
    __syncthreads();

    for (int idx = tid; idx < 64 * A_SZ; idx += 128) {
        int r = idx >> 7, a = idx & 127;
        float s = 0.f;
        #pragma unroll
        for (int e = 0; e < E_SZ; e++)
            s = fmaf(Wg[r][e], b_strat[e * A_SZ + a], s);
        out[(size_t)(b0 + r) * A_SZ + a] = s;
    }
}

// =====================================================================
// Main: fp16 m16n8k16. CTA 128x64, 512 threads, 16 warps as 2M x 8N.
// R9 pipeline (ring-8 W, 4-tile groups, 1 barrier/group) with split
// accumulator chains: per mt, two independent 2-HMMA chains. p0 merges
// immediately after its chain (shorter live range, less reg pressure);
// p1's chain has no dependence on p0's merge, so both chains still
// overlap in the tensor pipe.
// =====================================================================
#define NTT   512                        // 16 P-chunks * 32 experts
#define WSB   16384                      // w_s: 32 e * 64 float2
#define XOFF  WSB
#define XBUF  16384                      // 2 mblocks * 8KB
#define WOFF  (XOFF + 2 * XBUF)          // 49152
#define WSTG  8192
#define SMEM_TOT (WOFF + 8 * WSTG)       // 114688

__global__ __launch_bounds__(512, 1) void main_kernel(float* __restrict__ out)
{
    extern __shared__ char smem[];
    float2* w_s = (float2*)smem;         // [e][64] row-pairs
    const uint32_t sb = smem_u32(smem);
    const int tid = threadIdx.x;
    const int lane = tid & 31, wid = tid >> 5;
    const int wm = wid >> 3, wn = wid & 7;        // 2M x 8N
    const int g = lane >> 2, tg = lane & 3;
    const int b0 = blockIdx.x * 128;
    const int a0 = blockIdx.y * 64;

    // gating weights, pre-paired: pair p=(wm,mt,g) -> rows (row, row+8)
    for (int i = tid; i < E_SZ * 64; i += 512) {
        int e = i >> 6, p = i & 63;
        int row = (p >> 5) * 64 + ((p >> 3) & 3) * 16 + (p & 7);
        float2 w2;
        w2.x = g_weights[(size_t)(b0 + row) * E_SZ + e];
        w2.y = g_weights[(size_t)(b0 + row + 8) * E_SZ + e];
        w_s[i] = w2;
    }

    auto cp_x = [&](int P) {
        uint32_t base = sb + XOFF + (P & 1) * XBUF;
        #pragma unroll
        for (int j = 0; j < 2; j++) {
            int f = tid + j * 512;                // 0..1023 16B-units
            int mb = f >> 9, rem = f & 511;
            const char* src = (const char*)g_xh +
                              ((size_t)((blockIdx.x * 2 + mb) * 16 + P)) * 8192 + rem * 16;
            cp16(base + f * 16, src);
        }
    };
    // CTA-wide: all 512 threads load 16B each of the 8KB tile
    auto cp_w = [&](int t) {
        int P = t >> 5, e = t & 31;
        const char* src = (const char*)g_wh +
                          ((size_t)((e * 16 + P) * 16 + blockIdx.y * 8)) * 1024 + tid * 16;
        cp16(sb + WOFF + (t & 7) * WSTG + tid * 16, src);
    };

    // prologue: 4 groups, one per tile 0..3 (x rides with tile 0)
    cp_x(0); cp_w(0); CP_COMMIT();
    cp_w(1); CP_COMMIT();
    cp_w(2); CP_COMMIT();
    cp_w(3); CP_COMMIT();

    uint4 a_[2][2][4];                   // [dcsub][ks][mt]
    float master[4][4] = {};

    for (int T = 0; T < NTT; T += 4) {
        const int P = T >> 5;

        // prefetch next group's 4 tiles (one commit each; empty at tail ok)
        #pragma unroll
        for (int i = 0; i < 4; i++) {
            int tf = T + 4 + i;
            if (i == 0 && (T & 31) == 24 && P < 15) cp_x(P + 1);
            if (tf < NTT) cp_w(tf);
            CP_COMMIT();
        }
        CP_WAIT4();                      // groups for tiles <= T+3 complete
        __syncthreads();

        if ((T & 31) == 0) {             // chunk boundary: reload A frags
            const char* xb = smem + XOFF + (P & 1) * XBUF + wm * 8192;
            #pragma unroll
            for (int dcsub = 0; dcsub < 2; dcsub++)
                #pragma unroll
                for (int ks = 0; ks < 2; ks++)
                    #pragma unroll
                    for (int mt = 0; mt < 4; mt++) {
                        int fid = (dcsub * 2 + ks) * 4 + mt;
                        a_[dcsub][ks][mt] =
                            *(const uint4*)(xb + fid * 512 + lane * 16);
                    }
        }

        #pragma unroll
        for (int i = 0; i < 4; i++) {
            const int t = T + i, e = t & 31;
            const char* wb = smem + WOFF + (t & 7) * WSTG + wn * 1024;
            uint4 bfr0 = *(const uint4*)(wb + lane * 16);
            uint4 bfr1 = *(const uint4*)(wb + 512 + lane * 16);

            #pragma unroll
            for (int mt = 0; mt < 4; mt++) {
                float2 w2 = w_s[e * 64 + wm * 32 + mt * 8 + g];
                // chain 0 (dcsub=0): 2 dependent HMMAs, merge immediately
                float p0[4];
                mma16z(p0, a_[0][0][mt], bfr0.x, bfr0.y);
                // chain 1 (dcsub=1): independent of chain 0 and its merge
                float p1[4];
                mma16z(p1, a_[1][0][mt], bfr1.x, bfr1.y);
                mma16 (p0, a_[0][1][mt], bfr0.z, bfr0.w);
                mma16 (p1, a_[1][1][mt], bfr1.z, bfr1.w);
                master[mt][0] = fmaf(w2.x, p0[0], master[mt][0]);
                master[mt][1] = fmaf(w2.x, p0[1], master[mt][1]);
                master[mt][2] = fmaf(w2.y, p0[2], master[mt][2]);
                master[mt][3] = fmaf(w2.y, p0[3], master[mt][3]);
                master[mt][0] = fmaf(w2.x, p1[0], master[mt][0]);
                master[mt][1] = fmaf(w2.x, p1[1], master[mt][1]);
                master[mt][2] = fmaf(w2.y, p1[2], master[mt][2]);
                master[mt][3] = fmaf(w2.y, p1[3], master[mt][3]);
            }
        }
    }

    // epilogue: accumulate onto bias term already in out
    #pragma unroll
    for (int mt = 0; mt < 4; mt++) {
        int r = b0 + wm * 64 + mt * 16 + g;
        int c = a0 + wn * 8 + tg * 2;
        float2* q0 = (float2*)&out[(size_t)r * A_SZ + c];
        float2 v0 = *q0;
        v0.x += master[mt][0]; v0.y += master[mt][1];
        *q0 = v0;
        float2* q1 = (float2*)&out[(size_t)(r + 8) * A_SZ + c];
        float2 v1 = *q1;
        v1.x += master[mt][2]; v1.y += master[mt][3];
        *q1 = v1;
    }
}

// =====================================================================
extern "C" void kernel_launch(void* const* d_in, const int* in_sizes, int n_in,
                              void* d_out, int out_size) {
    const float* x       = (const float*)d_in[0];
    const float* W_att   = (const float*)d_in[1];
    const float* b_att   = (const float*)d_in[2];
    const float* abias   = (const float*)d_in[3];
    const float* W_strat = (const float*)d_in[4];
    const float* b_strat = (const float*)d_in[5];
    const float* gu      = (const float*)d_in[6];
    float* out = (float*)d_out;

    cudaFuncSetAttribute(main_kernel, cudaFuncAttributeMaxDynamicSharedMemorySize,
                         SMEM_TOT);

    convert_x_h<<<(B_SZ * D_SZ / 8) / 256, 256>>>(x);
    convert_w_h<<<(E_SZ * A_SZ * D_SZ / 8) / 256, 256>>>(W_strat);
    gating_kernel<<<B_SZ / 64, 128>>>(x, W_att, b_att, abias, b_strat, gu, out);
    main_kernel<<<dim3(B_SZ / 128, A_SZ / 64), 512, SMEM_TOT>>>(out);
}

// round 13
// speedup vs baseline: 1.0658x; 1.0658x over previous
#include <cuda_runtime.h>
#include <cuda_fp16.h>
#include <cstdint>

#define B_SZ 8192
#define D_SZ 1024
#define E_SZ 32
#define A_SZ 128

// gating weights; fragment-ordered fp16 operands
__device__ float g_weights[B_SZ * E_SZ];
__device__ uint4 g_xh[(size_t)B_SZ * D_SZ / 8];              // 16 MB (8 halves/uint4)
__device__ uint4 g_wh[(size_t)E_SZ * A_SZ * D_SZ / 8];       // 8 MB  (8 halves/uint4)

// ===================== helpers =====================
__device__ __forceinline__ uint32_t smem_u32(const void* p) {
    uint32_t a;
    asm("{ .reg .u64 t; cvta.to.shared.u64 t, %1; cvt.u32.u64 %0, t; }" : "=r"(a) : "l"(p));
    return a;
}
__device__ __forceinline__ uint32_t pk(float a, float b) {
    __half2 h = __floats2half2_rn(a, b);
    return *(uint32_t*)&h;
}
__device__ __forceinline__ void cp16(uint32_t dst, const void* src) {
    asm volatile("cp.async.cg.shared.global [%0], [%1], 16;" :: "r"(dst), "l"(src));
}
#define CP_COMMIT() asm volatile("cp.async.commit_group;" ::: "memory")
#define CP_WAIT4()  asm volatile("cp.async.wait_group 4;" ::: "memory")

// fp16 m16n8k16: D(f32) = A*B + C
__device__ __forceinline__ void mma16(float* c, const uint4& a, uint32_t b0, uint32_t b1) {
    asm volatile(
        "mma.sync.aligned.m16n8k16.row.col.f32.f16.f16.f32 "
        "{%0,%1,%2,%3}, {%4,%5,%6,%7}, {%8,%9}, {%0,%1,%2,%3};"
        : "+f"(c[0]), "+f"(c[1]), "+f"(c[2]), "+f"(c[3])
        : "r"(a.x), "r"(a.y), "r"(a.z), "r"(a.w), "r"(b0), "r"(b1));
}
__device__ __forceinline__ void mma16z(float* c, const uint4& a, uint32_t b0, uint32_t b1) {
    asm volatile(
        "mma.sync.aligned.m16n8k16.row.col.f32.f16.f16.f32 "
        "{%0,%1,%2,%3}, {%4,%5,%6,%7}, {%8,%9}, {%10,%10,%10,%10};"
        : "=f"(c[0]), "=f"(c[1]), "=f"(c[2]), "=f"(c[3])
        : "r"(a.x), "r"(a.y), "r"(a.z), "r"(a.w), "r"(b0), "r"(b1), "f"(0.0f));
}

// =====================================================================
// Prepass A: x -> fp16, fragment-ordered (64-row M0 blocks).
// g_xh[(M0*16 + P)*512 + fid*32 + lane] = uint4 A-fragment regs
// fid = (dcsub*2+ks)*4 + mt;  frag covers rows M0*64+mt*16..+15,
// k = P*64 + dcsub*32 + ks*16 .. +15.
// =====================================================================
__global__ __launch_bounds__(256) void convert_x_h(const float* __restrict__ x)
{
    int tid = blockIdx.x * 256 + threadIdx.x;         // 0 .. 1048575
    int lane = tid & 31, fid = (tid >> 5) & 15, P = (tid >> 9) & 15, M0 = tid >> 13;
    int mt = fid & 3, ks = (fid >> 2) & 1, dcsub = fid >> 3;
    int row = M0 * 64 + mt * 16 + (lane >> 2);
    int kb  = P * 64 + dcsub * 32 + ks * 16 + (lane & 3) * 2;
    const float* r0 = x + (size_t)row * D_SZ + kb;
    const float* r1 = r0 + 8 * D_SZ;
    uint4 o;
    o.x = pk(r0[0], r0[1]);      // a0: (row,   k..k+1)
    o.y = pk(r1[0], r1[1]);      // a1: (row+8, k..k+1)
    o.z = pk(r0[8], r0[9]);      // a2: (row,   k+8..k+9)
    o.w = pk(r1[8], r1[9]);      // a3: (row+8, k+8..k+9)
    g_xh[tid] = o;
}

// =====================================================================
// Prepass B: W_strat -> fp16, fragment-ordered.
// g_wh[(((e*16+P)*16 + cb)*2 + dcsub)*32 + lane] =
//   {ks0:b0,b1, ks1:b0,b1} for col a = cb*8 + lane/4.
// =====================================================================
__global__ __launch_bounds__(256) void convert_w_h(const float* __restrict__ W)
{
    int tid = blockIdx.x * 256 + threadIdx.x;         // 0 .. 524287
    int lane = tid & 31, dcsub = (tid >> 5) & 1, cb = (tid >> 6) & 15;
    int P = (tid >> 10) & 15, e = tid >> 14;          // e = 0..31
    int a  = cb * 8 + (lane >> 2);
    int tg = lane & 3;
    const float* base = W + ((size_t)e * A_SZ + a) * D_SZ + P * 64 + dcsub * 32 + tg * 2;
    uint4 o;
    o.x = pk(base[0],  base[1]);    // ks0 b0: k,k+1
    o.y = pk(base[8],  base[9]);    // ks0 b1: k+8,k+9
    o.z = pk(base[16], base[17]);   // ks1 b0
    o.w = pk(base[24], base[25]);   // ks1 b1
    g_wh[tid] = o;
}

// =====================================================================
// Kernel: gating (R1, known-correct). Seeds out with the b_strat bias term.
// =====================================================================
__global__ __launch_bounds__(128) void gating_kernel(
    const float* __restrict__ x, const float* __restrict__ W_att,
    const float* __restrict__ b_att, const float* __restrict__ abias,
    const float* __restrict__ b_strat, const float* __restrict__ gu,
    float* __restrict__ out)
{
    __shared__ float xs[32][64];
    __shared__ float was[32][32];
    __shared__ float L[64][33];
    __shared__ float Wg[64][33];

    const int tid = threadIdx.x;
    const int b0 = blockIdx.x * 64;
    const int tb = tid & 15;
    const int te = tid >> 4;

    float acc[4][4] = {};

    for (int d0 = 0; d0 < D_SZ; d0 += 32) {
        #pragma unroll
        for (int i = 0; i < 4; i++) {
            int f = tid + i * 128;
            int row = f >> 3, c4 = f & 7;
            float4 v = *(const float4*)&x[(size_t)(b0 + row) * D_SZ + d0 + c4 * 4];
            xs[c4 * 4 + 0][row] = v.x; xs[c4 * 4 + 1][row] = v.y;
            xs[c4 * 4 + 2][row] = v.z; xs[c4 * 4 + 3][row] = v.w;
        }
        #pragma unroll
        for (int i = 0; i < 2; i++) {
            int f = tid + i * 128;
            int row = f >> 3, c4 = f & 7;
            float4 v = *(const float4*)&W_att[(size_t)row * D_SZ + d0 + c4 * 4];
            was[c4 * 4 + 0][row] = v.x; was[c4 * 4 + 1][row] = v.y;
            was[c4 * 4 + 2][row] = v.z; was[c4 * 4 + 3][row] = v.w;
        }
        __syncthreads();
        #pragma unroll 8
        for (int kk = 0; kk < 32; kk++) {
            float4 av = *(const float4*)&xs[kk][tb * 4];
            float4 ev = *(const float4*)&was[kk][te * 4];
            float a_[4] = {av.x, av.y, av.z, av.w};
            float e_[4] = {ev.x, ev.y, ev.z, ev.w};
            #pragma unroll
            for (int i = 0; i < 4; i++)
                #pragma unroll
                for (int j = 0; j < 4; j++)
                    acc[i][j] = fmaf(a_[i], e_[j], acc[i][j]);
        }
        __syncthreads();
    }

    #pragma unroll
    for (int i = 0; i < 4; i++)
        #pragma unroll
        for (int j = 0; j < 4; j++)
            L[tb * 4 + i][te * 4 + j] = acc[i][j];
    __syncthreads();

    if (tid < 64) {
        int b = b0 + tid;
        float v[E_SZ];
        float mx = -1e30f;
        #pragma unroll
        for (int e = 0; e < E_SZ; e++) {
            float u = gu[(size_t)b * E_SZ + e];
            float g = -logf(-logf(u + 1e-10f) + 1e-10f);
            float t = L[tid][e] + b_att[e] + abias[e] + g;   // TAU = 1.0
            v[e] = t;
            mx = fmaxf(mx, t);
        }
        float s = 0.f;
        #pragma unroll
        for (int e = 0; e < E_SZ; e++) { v[e] = expf(v[e] - mx); s += v[e]; }
        float inv = 1.f / s;
        #pragma unroll
        for (int e = 0; e < E_SZ; e++) {
            float w = v[e] * inv;
            Wg[tid][e] = w;
            g_weights[(size_t)b * E_SZ + e] = w;
        }
    }
    __syncthreads();

    for (int idx = tid; idx < 64 * A_SZ; idx += 128) {
        int r = idx >> 7, a = idx & 127;
        float s = 0.f;
        #pragma unroll
        for (int e = 0; e < E_SZ; e++)
            s = fmaf(Wg[r][e], b_strat[e * A_SZ + a], s);
        out[(size_t)(b0 + r) * A_SZ + a] = s;
    }
}

// =====================================================================
// Main: fp16 m16n8k16. CTA 64x64, 256 threads, 8 warps (1M x 8N),
// 2 CTAs/SM (88KB smem, 128-reg cap). RACE-FREE pipeline: groups of 2
// tiles, ring-8 W, prefetch distance 4, barrier after wait. With skew
// <= 1 group (barrier-bounded), concurrent writes hit stages
// (T+6,T+7)&7 while slowest readers hit (T,T+1)&7 — always disjoint.
// =====================================================================
#define NTT   512                        // 16 P-chunks * 32 experts
#define WSB   8192                       // w_s: 32 e * 32 float2
#define XOFF  WSB
#define XBUF  8192                       // per x buffer (64 rows)
#define WOFF  (XOFF + 2 * XBUF)          // 24576
#define WSTG  8192
#define SMEM_TOT (WOFF + 8 * WSTG)       // 90112

__global__ __launch_bounds__(256, 2) void main_kernel(float* __restrict__ out)
{
    extern __shared__ char smem[];
    float2* w_s = (float2*)smem;         // [e][32] row-pairs
    const uint32_t sb = smem_u32(smem);
    const int tid = threadIdx.x;
    const int lane = tid & 31, wn = tid >> 5;     // 8 warps, all N-split
    const int g = lane >> 2, tg = lane & 3;
    const int b0 = blockIdx.x * 64;
    const int a0 = blockIdx.y * 64;

    // gating weights, pre-paired: pair p=(mt,g) -> rows (row, row+8)
    for (int i = tid; i < E_SZ * 32; i += 256) {
        int e = i >> 5, p = i & 31;
        int row = ((p >> 3) & 3) * 16 + (p & 7);
        float2 w2;
        w2.x = g_weights[(size_t)(b0 + row) * E_SZ + e];
        w2.y = g_weights[(size_t)(b0 + row + 8) * E_SZ + e];
        w_s[i] = w2;
    }

    auto cp_x = [&](int P) {
        uint32_t base = sb + XOFF + (P & 1) * XBUF;
        const char* src = (const char*)g_xh +
                          ((size_t)(blockIdx.x * 16 + P)) * 8192;
        cp16(base + tid * 16,        src + tid * 16);
        cp16(base + 4096 + tid * 16, src + 4096 + tid * 16);
    };
    // CTA-wide: 256 threads x 2 cp16 cover the 8KB W tile
    auto cp_w = [&](int t) {
        int P = t >> 5, e = t & 31;
        const char* src = (const char*)g_wh +
                          ((size_t)((e * 16 + P) * 16 + blockIdx.y * 8)) * 1024;
        uint32_t dst = sb + WOFF + (t & 7) * WSTG;
        cp16(dst + tid * 16,        src + tid * 16);
        cp16(dst + 4096 + tid * 16, src + 4096 + tid * 16);
    };

    // prologue: 4 commit groups = tiles 0..3 (x rides with tile 0)
    cp_x(0); cp_w(0); CP_COMMIT();
    cp_w(1); CP_COMMIT();
    cp_w(2); CP_COMMIT();
    cp_w(3); CP_COMMIT();

    uint4 a_[2][2][4];                   // [dcsub][ks][mt]
    float master[4][4] = {};

    for (int T = 0; T < NTT; T += 2) {
        const int P = T >> 5;

        // prefetch tiles T+4, T+5 (one commit each; empty at tail ok)
        if ((T & 31) == 24 && P < 15) cp_x(P + 1);
        if (T + 4 < NTT) cp_w(T + 4);
        CP_COMMIT();
        if (T + 5 < NTT) cp_w(T + 5);
        CP_COMMIT();
        CP_WAIT4();                      // own tiles <= T+1 (and x) landed
        __syncthreads();                 // => ALL threads' tiles <= T+1 landed

        if ((T & 31) == 0) {             // chunk boundary: reload A frags
            const char* xb = smem + XOFF + (P & 1) * XBUF;
            #pragma unroll
            for (int dcsub = 0; dcsub < 2; dcsub++)
                #pragma unroll
                for (int ks = 0; ks < 2; ks++)
                    #pragma unroll
                    for (int mt = 0; mt < 4; mt++) {
                        int fid = (dcsub * 2 + ks) * 4 + mt;
                        a_[dcsub][ks][mt] =
                            *(const uint4*)(xb + fid * 512 + lane * 16);
                    }
        }

        #pragma unroll
        for (int i = 0; i < 2; i++) {
            const int t = T + i, e = t & 31;
            const char* wb = smem + WOFF + (t & 7) * WSTG + wn * 1024;
            uint4 bfr0 = *(const uint4*)(wb + lane * 16);
            uint4 bfr1 = *(const uint4*)(wb + 512 + lane * 16);

            #pragma unroll
            for (int mt = 0; mt < 4; mt++) {
                float part[4];
                mma16z(part, a_[0][0][mt], bfr0.x, bfr0.y);
                mma16 (part, a_[0][1][mt], bfr0.z, bfr0.w);
                mma16 (part, a_[1][0][mt], bfr1.x, bfr1.y);
                mma16 (part, a_[1][1][mt], bfr1.z, bfr1.w);
                float2 w2 = w_s[e * 32 + mt * 8 + g];
                master[mt][0] = fmaf(w2.x, part[0], master[mt][0]);
                master[mt][1] = fmaf(w2.x, part[1], master[mt][1]);
                master[mt][2] = fmaf(w2.y, part[2], master[mt][2]);
                master[mt][3] = fmaf(w2.y, part[3], master[mt][3]);
            }
        }
    }

    // epilogue: accumulate onto bias term already in out
    #pragma unroll
    for (int mt = 0; mt < 4; mt++) {
        int r = b0 + mt * 16 + g;
        int c = a0 + wn * 8 + tg * 2;
        float2* q0 = (float2*)&out[(size_t)r * A_SZ + c];
        float2 v0 = *q0;
        v0.x += master[mt][0]; v0.y += master[mt][1];
        *q0 = v0;
        float2* q1 = (float2*)&out[(size_t)(r + 8) * A_SZ + c];
        float2 v1 = *q1;
        v1.x += master[mt][2]; v1.y += master[mt][3];
        *q1 = v1;
    }
}

// =====================================================================
extern "C" void kernel_launch(void* const* d_in, const int* in_sizes, int n_in,
                              void* d_out, int out_size) {
    const float* x       = (const float*)d_in[0];
    const float* W_att   = (const float*)d_in[1];
    const float* b_att   = (const float*)d_in[2];
    const float* abias   = (const float*)d_in[3];
    const float* W_strat = (const float*)d_in[4];
    const float* b_strat = (const float*)d_in[5];
    const float* gu      = (const float*)d_in[6];
    float* out = (float*)d_out;

    cudaFuncSetAttribute(main_kernel, cudaFuncAttributeMaxDynamicSharedMemorySize,
                         SMEM_TOT);

    convert_x_h<<<(B_SZ * D_SZ / 8) / 256, 256>>>(x);
    convert_w_h<<<(E_SZ * A_SZ * D_SZ / 8) / 256, 256>>>(W_strat);
    gating_kernel<<<B_SZ / 64, 128>>>(x, W_att, b_att, abias, b_strat, gu, out);
    main_kernel<<<dim3(B_SZ / 64, A_SZ / 64), 256, SMEM_TOT>>>(out);
}

// round 14
// speedup vs baseline: 1.1397x; 1.0694x over previous
#include <cuda_runtime.h>
#include <cuda_fp16.h>
#include <cstdint>

#define B_SZ 8192
#define D_SZ 1024
#define E_SZ 32
#define A_SZ 128

// gating weights; fragment-ordered fp16 operands
__device__ float g_weights[B_SZ * E_SZ];
__device__ uint4 g_xh[(size_t)B_SZ * D_SZ / 8];              // 16 MB (8 halves/uint4)
__device__ uint4 g_wh[(size_t)E_SZ * A_SZ * D_SZ / 8];       // 8 MB  (8 halves/uint4)

// ===================== helpers =====================
__device__ __forceinline__ uint32_t smem_u32(const void* p) {
    uint32_t a;
    asm("{ .reg .u64 t; cvta.to.shared.u64 t, %1; cvt.u32.u64 %0, t; }" : "=r"(a) : "l"(p));
    return a;
}
__device__ __forceinline__ uint32_t pk(float a, float b) {
    __half2 h = __floats2half2_rn(a, b);
    return *(uint32_t*)&h;
}
__device__ __forceinline__ void cp16(uint32_t dst, const void* src) {
    asm volatile("cp.async.cg.shared.global [%0], [%1], 16;" :: "r"(dst), "l"(src));
}
#define CP_COMMIT() asm volatile("cp.async.commit_group;" ::: "memory")
#define CP_WAIT4()  asm volatile("cp.async.wait_group 4;" ::: "memory")

// fp16 m16n8k16: D(f32) = A*B + C
__device__ __forceinline__ void mma16(float* c, const uint4& a, uint32_t b0, uint32_t b1) {
    asm volatile(
        "mma.sync.aligned.m16n8k16.row.col.f32.f16.f16.f32 "
        "{%0,%1,%2,%3}, {%4,%5,%6,%7}, {%8,%9}, {%0,%1,%2,%3};"
        : "+f"(c[0]), "+f"(c[1]), "+f"(c[2]), "+f"(c[3])
        : "r"(a.x), "r"(a.y), "r"(a.z), "r"(a.w), "r"(b0), "r"(b1));
}
__device__ __forceinline__ void mma16z(float* c, const uint4& a, uint32_t b0, uint32_t b1) {
    asm volatile(
        "mma.sync.aligned.m16n8k16.row.col.f32.f16.f16.f32 "
        "{%0,%1,%2,%3}, {%4,%5,%6,%7}, {%8,%9}, {%10,%10,%10,%10};"
        : "=f"(c[0]), "=f"(c[1]), "=f"(c[2]), "=f"(c[3])
        : "r"(a.x), "r"(a.y), "r"(a.z), "r"(a.w), "r"(b0), "r"(b1), "f"(0.0f));
}

// =====================================================================
// Prepass A: x -> fp16, fragment-ordered (64-row M0 blocks).
// g_xh[(M0*16 + P)*512 + fid*32 + lane] = uint4 A-fragment regs
// fid = (dcsub*2+ks)*4 + mt;  frag covers rows M0*64+mt*16..+15,
// k = P*64 + dcsub*32 + ks*16 .. +15.
// =====================================================================
__global__ __launch_bounds__(256) void convert_x_h(const float* __restrict__ x)
{
    int tid = blockIdx.x * 256 + threadIdx.x;         // 0 .. 1048575
    int lane = tid & 31, fid = (tid >> 5) & 15, P = (tid >> 9) & 15, M0 = tid >> 13;
    int mt = fid & 3, ks = (fid >> 2) & 1, dcsub = fid >> 3;
    int row = M0 * 64 + mt * 16 + (lane >> 2);
    int kb  = P * 64 + dcsub * 32 + ks * 16 + (lane & 3) * 2;
    const float* r0 = x + (size_t)row * D_SZ + kb;
    const float* r1 = r0 + 8 * D_SZ;
    uint4 o;
    o.x = pk(r0[0], r0[1]);      // a0: (row,   k..k+1)
    o.y = pk(r1[0], r1[1]);      // a1: (row+8, k..k+1)
    o.z = pk(r0[8], r0[9]);      // a2: (row,   k+8..k+9)
    o.w = pk(r1[8], r1[9]);      // a3: (row+8, k+8..k+9)
    g_xh[tid] = o;
}

// =====================================================================
// Prepass B: W_strat -> fp16, fragment-ordered.
// g_wh[(((e*16+P)*16 + cb)*2 + dcsub)*32 + lane] =
//   {ks0:b0,b1, ks1:b0,b1} for col a = cb*8 + lane/4.
// =====================================================================
__global__ __launch_bounds__(256) void convert_w_h(const float* __restrict__ W)
{
    int tid = blockIdx.x * 256 + threadIdx.x;         // 0 .. 524287
    int lane = tid & 31, dcsub = (tid >> 5) & 1, cb = (tid >> 6) & 15;
    int P = (tid >> 10) & 15, e = tid >> 14;          // e = 0..31
    int a  = cb * 8 + (lane >> 2);
    int tg = lane & 3;
    const float* base = W + ((size_t)e * A_SZ + a) * D_SZ + P * 64 + dcsub * 32 + tg * 2;
    uint4 o;
    o.x = pk(base[0],  base[1]);    // ks0 b0: k,k+1
    o.y = pk(base[8],  base[9]);    // ks0 b1: k+8,k+9
    o.z = pk(base[16], base[17]);   // ks1 b0
    o.w = pk(base[24], base[25]);   // ks1 b1
    g_wh[tid] = o;
}

// =====================================================================
// Kernel: gating (R1, known-correct). Seeds out with the b_strat bias term.
// =====================================================================
__global__ __launch_bounds__(128) void gating_kernel(
    const float* __restrict__ x, const float* __restrict__ W_att,
    const float* __restrict__ b_att, const float* __restrict__ abias,
    const float* __restrict__ b_strat, const float* __restrict__ gu,
    float* __restrict__ out)
{
    __shared__ float xs[32][64];
    __shared__ float was[32][32];
    __shared__ float L[64][33];
    __shared__ float Wg[64][33];

    const int tid = threadIdx.x;
    const int b0 = blockIdx.x * 64;
    const int tb = tid & 15;
    const int te = tid >> 4;

    float acc[4][4] = {};

    for (int d0 = 0; d0 < D_SZ; d0 += 32) {
        #pragma unroll
        for (int i = 0; i < 4; i++) {
            int f = tid + i * 128;
            int row = f >> 3, c4 = f & 7;
            float4 v = *(const float4*)&x[(size_t)(b0 + row) * D_SZ + d0 + c4 * 4];
            xs[c4 * 4 + 0][row] = v.x; xs[c4 * 4 + 1][row] = v.y;
            xs[c4 * 4 + 2][row] = v.z; xs[c4 * 4 + 3][row] = v.w;
        }
        #pragma unroll
        for (int i = 0; i < 2; i++) {
            int f = tid + i * 128;
            int row = f >> 3, c4 = f & 7;
            float4 v = *(const float4*)&W_att[(size_t)row * D_SZ + d0 + c4 * 4];
            was[c4 * 4 + 0][row] = v.x; was[c4 * 4 + 1][row] = v.y;
            was[c4 * 4 + 2][row] = v.z; was[c4 * 4 + 3][row] = v.w;
        }
        __syncthreads();
        #pragma unroll 8
        for (int kk = 0; kk < 32; kk++) {
            float4 av = *(const float4*)&xs[kk][tb * 4];
            float4 ev = *(const float4*)&was[kk][te * 4];
            float a_[4] = {av.x, av.y, av.z, av.w};
            float e_[4] = {ev.x, ev.y, ev.z, ev.w};
            #pragma unroll
            for (int i = 0; i < 4; i++)
                #pragma unroll
                for (int j = 0; j < 4; j++)
                    acc[i][j] = fmaf(a_[i], e_[j], acc[i][j]);
        }
        __syncthreads();
    }

    #pragma unroll
    for (int i = 0; i < 4; i++)
        #pragma unroll
        for (int j = 0; j < 4; j++)
            L[tb * 4 + i][te * 4 + j] = acc[i][j];
    __syncthreads();

    if (tid < 64) {
        int b = b0 + tid;
        float v[E_SZ];
        float mx = -1e30f;
        #pragma unroll
        for (int e = 0; e < E_SZ; e++) {
            float u = gu[(size_t)b * E_SZ + e];
            float g = -logf(-logf(u + 1e-10f) + 1e-10f);
            float t = L[tid][e] + b_att[e] + abias[e] + g;   // TAU = 1.0
            v[e] = t;
            mx = fmaxf(mx, t);
        }
        float s = 0.f;
        #pragma unroll
        for (int e = 0; e < E_SZ; e++) { v[e] = expf(v[e] - mx); s += v[e]; }
        float inv = 1.f / s;
        #pragma unroll
        for (int e = 0; e < E_SZ; e++) {
            float w = v[e] * inv;
            Wg[tid][e] = w;
            g_weights[(size_t)b * E_SZ + e] = w;
        }
    }
    __syncthreads();

    for (int idx = tid; idx < 64 * A_SZ; idx += 128) {
        int r = idx >> 7, a = idx & 127;
        float s = 0.f;
        #pragma unroll
        for (int e = 0; e < E_SZ; e++)
            s = fmaf(Wg[r][e], b_strat[e * A_SZ + a], s);
        out[(size_t)(b0 + r) * A_SZ + a] = s;
    }
}

// =====================================================================
// Main: fp16 m16n8k16. CTA 128x64, 512 threads, 16 warps as 2M x 8N
// (R9 shape: half the W traffic / cp instructions of R13).
// RACE-FREE pipeline (R13 proof): ring-8 W, groups of 2 tiles,
// prefetch distance 4, barrier AFTER wait; skew <= 1 group means
// writers hit stages (T+6,T+7)&7 while slowest readers hit (T,T+1)&7.
// BATCHED B loads: both tiles' fragments loaded right after the
// barrier so LDS latency overlaps the first tile's HMMA stream.
// =====================================================================
#define NTT   512                        // 16 P-chunks * 32 experts
#define WSB   16384                      // w_s: 32 e * 64 float2
#define XOFF  WSB
#define XBUF  16384                      // 2 mblocks * 8KB
#define WOFF  (XOFF + 2 * XBUF)          // 49152
#define WSTG  8192
#define SMEM_TOT (WOFF + 8 * WSTG)       // 114688

__global__ __launch_bounds__(512, 1) void main_kernel(float* __restrict__ out)
{
    extern __shared__ char smem[];
    float2* w_s = (float2*)smem;         // [e][64] row-pairs
    const uint32_t sb = smem_u32(smem);
    const int tid = threadIdx.x;
    const int lane = tid & 31, wid = tid >> 5;
    const int wm = wid >> 3, wn = wid & 7;        // 2M x 8N
    const int g = lane >> 2, tg = lane & 3;
    const int b0 = blockIdx.x * 128;
    const int a0 = blockIdx.y * 64;

    // gating weights, pre-paired: pair p=(wm,mt,g) -> rows (row, row+8)
    for (int i = tid; i < E_SZ * 64; i += 512) {
        int e = i >> 6, p = i & 63;
        int row = (p >> 5) * 64 + ((p >> 3) & 3) * 16 + (p & 7);
        float2 w2;
        w2.x = g_weights[(size_t)(b0 + row) * E_SZ + e];
        w2.y = g_weights[(size_t)(b0 + row + 8) * E_SZ + e];
        w_s[i] = w2;
    }

    auto cp_x = [&](int P) {
        uint32_t base = sb + XOFF + (P & 1) * XBUF;
        #pragma unroll
        for (int j = 0; j < 2; j++) {
            int f = tid + j * 512;                // 0..1023 16B-units
            int mb = f >> 9, rem = f & 511;
            const char* src = (const char*)g_xh +
                              ((size_t)((blockIdx.x * 2 + mb) * 16 + P)) * 8192 + rem * 16;
            cp16(base + f * 16, src);
        }
    };
    // CTA-wide: all 512 threads load 16B each of the 8KB W tile
    auto cp_w = [&](int t) {
        int P = t >> 5, e = t & 31;
        const char* src = (const char*)g_wh +
                          ((size_t)((e * 16 + P) * 16 + blockIdx.y * 8)) * 1024 + tid * 16;
        cp16(sb + WOFF + (t & 7) * WSTG + tid * 16, src);
    };

    // prologue: 4 commit groups = tiles 0..3 (x rides with tile 0)
    cp_x(0); cp_w(0); CP_COMMIT();
    cp_w(1); CP_COMMIT();
    cp_w(2); CP_COMMIT();
    cp_w(3); CP_COMMIT();

    uint4 a_[2][2][4];                   // [dcsub][ks][mt]
    float master[4][4] = {};

    for (int T = 0; T < NTT; T += 2) {
        const int P = T >> 5;

        // prefetch tiles T+4, T+5 (one commit each; empty at tail ok)
        if ((T & 31) == 24 && P < 15) cp_x(P + 1);
        if (T + 4 < NTT) cp_w(T + 4);
        CP_COMMIT();
        if (T + 5 < NTT) cp_w(T + 5);
        CP_COMMIT();
        CP_WAIT4();                      // own tiles <= T+1 (and x) landed
        __syncthreads();                 // => ALL threads' tiles <= T+1 landed

        if ((T & 31) == 0) {             // chunk boundary: reload A frags
            const char* xb = smem + XOFF + (P & 1) * XBUF + wm * 8192;
            #pragma unroll
            for (int dcsub = 0; dcsub < 2; dcsub++)
                #pragma unroll
                for (int ks = 0; ks < 2; ks++)
                    #pragma unroll
                    for (int mt = 0; mt < 4; mt++) {
                        int fid = (dcsub * 2 + ks) * 4 + mt;
                        a_[dcsub][ks][mt] =
                            *(const uint4*)(xb + fid * 512 + lane * 16);
                    }
        }

        // batched B-fragment loads for BOTH tiles of the group
        const char* wb0 = smem + WOFF + (T & 7) * WSTG + wn * 1024;
        const char* wb1 = smem + WOFF + ((T + 1) & 7) * WSTG + wn * 1024;
        uint4 b00 = *(const uint4*)(wb0 + lane * 16);
        uint4 b01 = *(const uint4*)(wb0 + 512 + lane * 16);
        uint4 b10 = *(const uint4*)(wb1 + lane * 16);
        uint4 b11 = *(const uint4*)(wb1 + 512 + lane * 16);

        // tile T (expert e0) then tile T+1 (expert e0+1)
        const int e0 = T & 31;
        #pragma unroll
        for (int mt = 0; mt < 4; mt++) {
            float part[4];
            mma16z(part, a_[0][0][mt], b00.x, b00.y);
            mma16 (part, a_[0][1][mt], b00.z, b00.w);
            mma16 (part, a_[1][0][mt], b01.x, b01.y);
            mma16 (part, a_[1][1][mt], b01.z, b01.w);
            float2 w2 = w_s[e0 * 64 + wm * 32 + mt * 8 + g];
            master[mt][0] = fmaf(w2.x, part[0], master[mt][0]);
            master[mt][1] = fmaf(w2.x, part[1], master[mt][1]);
            master[mt][2] = fmaf(w2.y, part[2], master[mt][2]);
            master[mt][3] = fmaf(w2.y, part[3], master[mt][3]);
        }
        #pragma unroll
        for (int mt = 0; mt < 4; mt++) {
            float part[4];
            mma16z(part, a_[0][0][mt], b10.x, b10.y);
            mma16 (part, a_[0][1][mt], b10.z, b10.w);
            mma16 (part, a_[1][0][mt], b11.x, b11.y);
            mma16 (part, a_[1][1][mt], b11.z, b11.w);
            float2 w2 = w_s[(e0 + 1) * 64 + wm * 32 + mt * 8 + g];
            master[mt][0] = fmaf(w2.x, part[0], master[mt][0]);
            master[mt][1] = fmaf(w2.x, part[1], master[mt][1]);
            master[mt][2] = fmaf(w2.y, part[2], master[mt][2]);
            master[mt][3] = fmaf(w2.y, part[3], master[mt][3]);
        }
    }

    // epilogue: accumulate onto bias term already in out
    #pragma unroll
    for (int mt = 0; mt < 4; mt++) {
        int r = b0 + wm * 64 + mt * 16 + g;
        int c = a0 + wn * 8 + tg * 2;
        float2* q0 = (float2*)&out[(size_t)r * A_SZ + c];
        float2 v0 = *q0;
        v0.x += master[mt][0]; v0.y += master[mt][1];
        *q0 = v0;
        float2* q1 = (float2*)&out[(size_t)(r + 8) * A_SZ + c];
        float2 v1 = *q1;
        v1.x += master[mt][2]; v1.y += master[mt][3];
        *q1 = v1;
    }
}

// =====================================================================
extern "C" void kernel_launch(void* const* d_in, const int* in_sizes, int n_in,
                              void* d_out, int out_size) {
    const float* x       = (const float*)d_in[0];
    const float* W_att   = (const float*)d_in[1];
    const float* b_att   = (const float*)d_in[2];
    const float* abias   = (const float*)d_in[3];
    const float* W_strat = (const float*)d_in[4];
    const float* b_strat = (const float*)d_in[5];
    const float* gu      = (const float*)d_in[6];
    float* out = (float*)d_out;

    cudaFuncSetAttribute(main_kernel, cudaFuncAttributeMaxDynamicSharedMemorySize,
                         SMEM_TOT);

    convert_x_h<<<(B_SZ * D_SZ / 8) / 256, 256>>>(x);
    convert_w_h<<<(E_SZ * A_SZ * D_SZ / 8) / 256, 256>>>(W_strat);
    gating_kernel<<<B_SZ / 64, 128>>>(x, W_att, b_att, abias, b_strat, gu, out);
    main_kernel<<<dim3(B_SZ / 128, A_SZ / 64), 512, SMEM_TOT>>>(out);
}